// round 15
// baseline (speedup 1.0000x reference)
#include <cuda_runtime.h>
#include <math_constants.h>

#define BB 8
#define NN 4096
#define NS 1024
#define SEGS 8
#define ROWS_PER_SEG 128          // NS / SEGS
#define STHREADS 512              // serial kernel block size

// Device scratch (no allocation allowed; __device__ globals are the escape hatch).
__device__ float4 g_p1[BB * NS];
__device__ float4 g_p2[BB * NS];
__device__ unsigned long long g_rowKey[BB * NS];
__device__ unsigned long long g_rowSec[BB * NS];
__device__ float g_batchLoss[BB];
__device__ unsigned g_done;

// Key layout: [63:32] d2 bits  [31:16] row id  [15:0] col id
// Lexicographic u64 order == reference's row-major (value,row,col) argmin order.
// Dead/invalid sentinel = ~0ULL.
#define MKKEY(vb, rid, cs) ((((unsigned long long)(vb)) << 32) | \
                            ((unsigned)(rid) << 16) | (unsigned)(cs))

// ===================== init: chip-parallel best-2 per row =====================
__global__ __launch_bounds__(ROWS_PER_SEG, 1)
void emd_init_kernel(const float* __restrict__ S1,
                     const float* __restrict__ S2,
                     const int*   __restrict__ idxs) {
    __shared__ float4 p2s[NS];            // 16 KB

    const int seg = blockIdx.x;
    const int b   = blockIdx.y;
    const int t   = threadIdx.x;

    if (seg == 0 && b == 0 && t == 0) g_done = 0;   // reset finisher counter

    for (int i = t; i < NS; i += ROWS_PER_SEG) {
        int id = idxs[b * NS + i];
        const float* q2 = S2 + ((long)b * NN + id) * 3;
        float4 f = make_float4(q2[0], q2[1], q2[2], __int_as_float(i));
        p2s[i] = f;
        if (seg == 0) g_p2[b * NS + i] = f;   // one block persists the col points
    }
    __syncthreads();

    const int row = seg * ROWS_PER_SEG + t;
    int id = idxs[b * NS + row];
    const float* q1 = S1 + ((long)b * NN + id) * 3;
    float4 p = make_float4(q1[0], q1[1], q1[2], 0.f);
    g_p1[b * NS + row] = p;

    float b1 = CUDART_INF_F, b2 = CUDART_INF_F;
    int   c1 = 0, c2 = 0;
    #pragma unroll 4
    for (int c = 0; c < NS; ++c) {            // uniform c -> LDS broadcast
        float4 q = p2s[c];
        float dx = p.x - q.x, dy = p.y - q.y, dz = p.z - q.z;
        float d2 = fmaf(dz, dz, fmaf(dy, dy, dx * dx));
        if (d2 < b1)      { b2 = b1; c2 = c1; b1 = d2; c1 = c; }
        else if (d2 < b2) { b2 = d2; c2 = c; }   // strict <: lowest col on ties
    }
    g_rowKey[b * NS + row] = MKKEY(__float_as_uint(b1), row, c1);
    g_rowSec[b * NS + row] = MKKEY(__float_as_uint(b2), row, c2);
}

// ===================== serial: one warp per batch greedy chain ================
struct SmemLayout {
    float4 p1s[NS];                  // 16 KB
    float4 p2sC[NS];                 // 16 KB  compact; .w = col id
    unsigned long long rowKey[NS];   //  8 KB  best key (~0 = dead row)
    unsigned long long rowSec[NS];   //  8 KB  2nd-best key (~0 = invalid)
    unsigned short colPos[NS];       //  2 KB
    unsigned char  colAlive[NS];     //  1 KB
};
#define SMEM_BYTES ((int)sizeof(SmemLayout))

__global__ __launch_bounds__(STHREADS, 1)
void emd_serial_kernel(float* __restrict__ out) {
    extern __shared__ char smem_raw[];
    SmemLayout* sm = reinterpret_cast<SmemLayout*>(smem_raw);
    float4* p1s  = sm->p1s;
    float4* p2sC = sm->p2sC;
    unsigned long long* rowKey = sm->rowKey;
    unsigned long long* rowSec = sm->rowSec;
    unsigned short* colPos = sm->colPos;
    unsigned char*  colAlive = sm->colAlive;

    const int b = blockIdx.x;
    const int t = threadIdx.x;

    // ---- reload precomputed state (contiguous, coalesced) ----
    for (int i = t; i < NS; i += STHREADS) {
        p1s[i]    = g_p1[b * NS + i];
        p2sC[i]   = g_p2[b * NS + i];
        rowKey[i] = g_rowKey[b * NS + i];
        rowSec[i] = g_rowSec[b * NS + i];
        colPos[i]   = (unsigned short)i;
        colAlive[i] = 1;
    }
    __syncthreads();

    if (t >= 32) return;   // single warp runs the sequential greedy chain

    const unsigned FULL = 0xffffffffu;
    const int lane = t;
    const int segBase = lane * 32;
    float loss = 0.f;

    // lane-local exact top-2 rebuild over this lane's 32 rowKeys (2 chains)
    auto rebuild2 = [&](unsigned long long& o1, unsigned long long& o2) {
        unsigned long long x1 = ~0ULL, x2 = ~0ULL, y1 = ~0ULL, y2 = ~0ULL;
        #pragma unroll
        for (int i = 0; i < 32; i += 2) {
            unsigned long long a = rowKey[segBase + i];
            unsigned long long c = rowKey[segBase + i + 1];
            if (a < x1) { x2 = x1; x1 = a; } else if (a < x2) { x2 = a; }
            if (c < y1) { y2 = y1; y1 = c; } else if (c < y2) { y2 = c; }
        }
        if (x1 < y1) { o1 = x1; o2 = (x2 < y1) ? x2 : y1; }
        else         { o1 = y1; o2 = (y2 < x1) ? y2 : x1; }
    };

    // s1 = EXACT segment min key; s2 = exact second (when s2ok)
    unsigned long long s1, s2;
    bool s2ok, needRb = false;
    rebuild2(s1, s2); s2ok = true;

    for (int it = 0; it < NS; ++it) {
        const int nAlive = NS - it;

        // ======== validation: every lane certifies its s1 (parallel) ========
        for (;;) {
            bool myNeed = false; int myRow = 0;
            if (needRb) { rebuild2(s1, s2); s2ok = true; needRb = false; }

            // lane-local repair chain: pure LDS/registers, concurrent per lane
            while (s1 != ~0ULL) {
                if (colAlive[(int)(s1 & 0xFFFFu)]) break;    // s1 exact & alive
                int r = (int)((s1 >> 16) & 0xFFFFu);
                unsigned long long sec = rowSec[r];
                if (sec == ~0ULL || !colAlive[(int)(sec & 0xFFFFu)]) {
                    myNeed = true; myRow = r; break;         // needs warp rescan
                }
                rowKey[r] = sec; rowSec[r] = ~0ULL;          // exact promotion
                if (s2ok && sec < s2)  s1 = sec;
                else if (s2ok)       { s1 = s2; s2ok = false; }
                else                 { rebuild2(s1, s2); s2ok = true; }
            }

            unsigned help = __ballot_sync(FULL, myNeed);
            if (!help) break;
            __syncwarp(FULL);                  // lane writes -> cooperative reads

            while (help) {                     // warp-cooperative rescans (rare)
                int src = __ffs(help) - 1; help &= help - 1;
                int r = __shfl_sync(FULL, myRow, src);
                float4 p = p1s[r];
                unsigned long long kb1 = ~0ULL, kb2 = ~0ULL;
                #pragma unroll 4
                for (int j = lane; j < nAlive; j += 32) {
                    float4 q = p2sC[j];
                    float dx = p.x - q.x, dy = p.y - q.y, dz = p.z - q.z;
                    float d2 = fmaf(dz, dz, fmaf(dy, dy, dx * dx));
                    unsigned long long k =
                        (((unsigned long long)__float_as_uint(d2)) << 10) |
                        (unsigned)__float_as_int(q.w);
                    if (k < kb1)      { kb2 = kb1; kb1 = k; }
                    else if (k < kb2) { kb2 = k; }
                }
                #pragma unroll
                for (int off = 16; off > 0; off >>= 1) {   // butterfly best-2
                    unsigned long long o1 = __shfl_xor_sync(FULL, kb1, off);
                    unsigned long long o2 = __shfl_xor_sync(FULL, kb2, off);
                    unsigned long long n1 = (o1 < kb1) ? o1 : kb1;
                    unsigned long long mx = (o1 < kb1) ? kb1 : o1;
                    unsigned long long n2 = (o2 < kb2) ? o2 : kb2;
                    kb1 = n1; kb2 = (mx < n2) ? mx : n2;
                }
                unsigned long long kn =
                    MKKEY((unsigned)(kb1 >> 10), r, (unsigned)(kb1 & 0x3FFu));
                if (lane == 0) {
                    rowKey[r] = kn;
                    rowSec[r] = (kb2 == ~0ULL) ? ~0ULL
                        : MKKEY((unsigned)(kb2 >> 10), r, (unsigned)(kb2 & 0x3FFu));
                }
                if (lane == src) {             // register-level seg update
                    if (s2ok && kn < s2)  s1 = kn;
                    else if (s2ok)      { s1 = s2; s2ok = false; }
                    else                  needRb = true;   // next round rebuilds
                }
            }
            __syncwarp(FULL);                  // rescan writes -> lane reads
        }

        // ======== pop: all 32 s1 are exact -> single always-valid round ====
        unsigned hi  = (unsigned)(s1 >> 32);
        unsigned lo  = (unsigned)s1;
        unsigned mhi = __reduce_min_sync(FULL, hi);
        unsigned mlo = __reduce_min_sync(FULL, (hi == mhi) ? lo : 0xFFFFFFFFu);
        float v  = __uint_as_float(mhi);
        int rid  = (int)(mlo >> 16);
        int csel = (int)(mlo & 0xFFFFu);

        // ======== accept: register seg update, no segment recompute ====
        const int lastP = nAlive - 1;
        float4 fLast = p2sC[lastP];            // independent broadcast loads
        int cpos = colPos[csel];
        if (lane == 0) {
            loss += sqrtf(v);                  // reference accumulation order
            rowKey[rid] = ~0ULL;
            p2sC[cpos] = fLast;                // col id rides in .w
            colPos[(unsigned)__float_as_int(fLast.w)] = (unsigned short)cpos;
            colAlive[csel] = 0;
        }
        if (lane == (rid >> 5)) {              // owner: consume s2 (exact)
            if (s2ok) { s1 = s2; s2ok = false; }
            else        needRb = true;
        }
        __syncwarp(FULL);                      // accept writes -> next validation
    }

    // ---- deterministic finisher: last block sums in fixed order ----
    if (lane == 0) {
        g_batchLoss[b] = loss / (float)NS;
        __threadfence();
        unsigned old = atomicAdd(&g_done, 1u);
        if (old == BB - 1) {
            float s = 0.f;
            #pragma unroll
            for (int i = 0; i < BB; ++i) s += g_batchLoss[i];
            out[0] = s / (float)BB;
        }
    }
}

extern "C" void kernel_launch(void* const* d_in, const int* in_sizes, int n_in,
                              void* d_out, int out_size) {
    const float* S1  = (const float*)d_in[0];
    const float* S2  = (const float*)d_in[1];
    const int*   idx = (const int*)  d_in[2];
    float* out = (float*)d_out;

    // Opt in to >48KB dynamic shared memory (non-stream API: immediate,
    // alloc-free, idempotent — safe under graph capture).
    cudaFuncSetAttribute(emd_serial_kernel,
                         cudaFuncAttributeMaxDynamicSharedMemorySize, SMEM_BYTES);

    emd_init_kernel<<<dim3(SEGS, BB), ROWS_PER_SEG>>>(S1, S2, idx);
    emd_serial_kernel<<<BB, STHREADS, SMEM_BYTES>>>(out);
}